// round 7
// baseline (speedup 1.0000x reference)
#include <cuda_runtime.h>
#include <math.h>

#define N_RES  8192
#define N_IN   128
#define BATCH  16
#define LEAK   0.9f
#define NQ     4                      // column quarters
#define QROWS  2048                   // rows per quarter
#define NBIN   (N_RES * NQ)           // 32768 fine bins (row, quarter)
#define QCAP   320                    // per-bin capacity; Poisson(205) + 8 sigma
#define NCH    148                    // stream chunks (= hist/place blocks)
#define GROWS  64                     // rows per gather block
#define SMEM_128K (NBIN * (int)sizeof(int))          // 128 KB
#define GATHER_SMEM (QROWS * BATCH * (int)sizeof(float))  // 128 KB

// ---------------------------------------------------------------------------
// Scratch (allocation-free __device__ globals)
__device__ __align__(16) float g_z[N_RES * BATCH];          // bias + input-spmm acc
__device__ __align__(16) float g_state_T[N_RES * BATCH];    // [row][batch]
__device__ __align__(16) float g_x_T[N_IN * BATCH];
__device__ unsigned int g_H [NCH * NBIN];                    // per-chunk histograms
__device__ unsigned int g_Hp[NCH * NBIN];                    // exclusive prefix over chunks
__device__ unsigned int g_total[NBIN];                       // per-bin totals
__device__ __align__(16) float2 g_bucket[(size_t)NBIN * QCAP];  // 84 MB sorted entries

__device__ __forceinline__ void red_add_v4(float* p, float a, float b, float c, float d) {
    asm volatile("red.global.add.v4.f32 [%0], {%1,%2,%3,%4};"
                 :: "l"(p), "f"(a), "f"(b), "f"(c), "f"(d) : "memory");
}

// ---------------------------------------------------------------------------
// Kernel 1: init z with biases, transpose state and x.
__global__ void k_init(const float* __restrict__ state,
                       const float* __restrict__ x,
                       const float* __restrict__ res_bias,
                       const float* __restrict__ in_bias) {
    int i = blockIdx.x * blockDim.x + threadIdx.x;
    if (i < N_RES * BATCH) {
        int r = i >> 4;
        int b = i & (BATCH - 1);
        g_z[i]       = res_bias[r] + in_bias[r];
        g_state_T[i] = state[b * N_RES + r];
    }
    if (i < N_IN * BATCH) {
        int r = i >> 4;
        int b = i & (BATCH - 1);
        g_x_T[i] = x[b * N_IN + r];
    }
}

// ---------------------------------------------------------------------------
// Kernel 2: per-chunk histogram over (row, quarter) bins. smem atomics only.
__global__ void __launch_bounds__(1024) k_hist(const int* __restrict__ rows,
                                               const int* __restrict__ cols,
                                               int nnz, int csz) {
    extern __shared__ unsigned int cnt[];          // NBIN u32 = 128 KB
    int tid = threadIdx.x;
    int ch  = blockIdx.x;
    for (int b = tid; b < NBIN; b += 1024) cnt[b] = 0;
    __syncthreads();

    int start = ch * csz;
    int end   = min(nnz, start + csz);
    for (int i = start + tid * 4; i < end; i += 1024 * 4) {
        if (i + 4 <= end) {
            int4 r4 = *(const int4*)(rows + i);
            int4 c4 = *(const int4*)(cols + i);
            atomicAdd(&cnt[(r4.x << 2) | (c4.x >> 11)], 1u);
            atomicAdd(&cnt[(r4.y << 2) | (c4.y >> 11)], 1u);
            atomicAdd(&cnt[(r4.z << 2) | (c4.z >> 11)], 1u);
            atomicAdd(&cnt[(r4.w << 2) | (c4.w >> 11)], 1u);
        } else {
            for (int k = i; k < end; k++)
                atomicAdd(&cnt[(rows[k] << 2) | (cols[k] >> 11)], 1u);
        }
    }
    __syncthreads();
    unsigned int* H = g_H + (size_t)ch * NBIN;
    for (int b = tid; b < NBIN; b += 1024) H[b] = cnt[b];   // coalesced 128 KB
}

// ---------------------------------------------------------------------------
// Kernel 3: per-bin exclusive scan across chunks; also bin totals.
__global__ void __launch_bounds__(1024) k_scan() {
    int bin = blockIdx.x * 1024 + threadIdx.x;     // 32 blocks
    unsigned int run = 0;
#pragma unroll 4
    for (int k = 0; k < NCH; k++) {
        unsigned int v = g_H[(size_t)k * NBIN + bin];
        g_Hp[(size_t)k * NBIN + bin] = run;
        run += v;
    }
    g_total[bin] = run;
}

// ---------------------------------------------------------------------------
// Kernel 4 (ncu slot): place entries into static per-bin segments.
// Rank = smem cursor (seeded from Hp) -> plain scattered 8B store. No global atomics.
__global__ void __launch_bounds__(1024) k_place(const float* __restrict__ vals,
                                                const int*   __restrict__ rows,
                                                const int*   __restrict__ cols,
                                                int nnz, int csz) {
    extern __shared__ unsigned int cur[];          // NBIN u32 = 128 KB
    int tid = threadIdx.x;
    int ch  = blockIdx.x;
    const unsigned int* Hp = g_Hp + (size_t)ch * NBIN;
    for (int b = tid; b < NBIN; b += 1024) cur[b] = Hp[b];  // coalesced 128 KB
    __syncthreads();

    int start = ch * csz;
    int end   = min(nnz, start + csz);
    for (int i = start + tid * 4; i < end; i += 1024 * 4) {
        if (i + 4 <= end) {
            int4   r4 = *(const int4*)(rows + i);
            int4   c4 = *(const int4*)(cols + i);
            float4 v4 = *(const float4*)(vals + i);
            int bin; unsigned int p;
            bin = (r4.x << 2) | (c4.x >> 11); p = atomicAdd(&cur[bin], 1u);
            if (p < QCAP) g_bucket[(size_t)bin * QCAP + p] = make_float2(v4.x, __int_as_float(c4.x));
            bin = (r4.y << 2) | (c4.y >> 11); p = atomicAdd(&cur[bin], 1u);
            if (p < QCAP) g_bucket[(size_t)bin * QCAP + p] = make_float2(v4.y, __int_as_float(c4.y));
            bin = (r4.z << 2) | (c4.z >> 11); p = atomicAdd(&cur[bin], 1u);
            if (p < QCAP) g_bucket[(size_t)bin * QCAP + p] = make_float2(v4.z, __int_as_float(c4.z));
            bin = (r4.w << 2) | (c4.w >> 11); p = atomicAdd(&cur[bin], 1u);
            if (p < QCAP) g_bucket[(size_t)bin * QCAP + p] = make_float2(v4.w, __int_as_float(c4.w));
        } else {
            for (int k = i; k < end; k++) {
                int bin = (rows[k] << 2) | (cols[k] >> 11);
                unsigned int p = atomicAdd(&cur[bin], 1u);
                if (p < QCAP) g_bucket[(size_t)bin * QCAP + p] =
                    make_float2(vals[k], __int_as_float(cols[k]));
            }
        }
    }
}

// ---------------------------------------------------------------------------
// Kernel 5: input SpMM (small).
__global__ void k_in_spmm(const float* __restrict__ vals,
                          const int*   __restrict__ rows,
                          const int*   __restrict__ cols,
                          int nnz) {
    int i = blockIdx.x * blockDim.x + threadIdx.x;
    if (i >= nnz) return;
    float v = vals[i];
    int r = rows[i];
    int c = cols[i];
    const float4* s = reinterpret_cast<const float4*>(g_x_T + c * BATCH);
    float4 s0 = s[0], s1 = s[1], s2 = s[2], s3 = s[3];
    float* zp = g_z + r * BATCH;
    red_add_v4(zp + 0,  v * s0.x, v * s0.y, v * s0.z, v * s0.w);
    red_add_v4(zp + 4,  v * s1.x, v * s1.y, v * s1.z, v * s1.w);
    red_add_v4(zp + 8,  v * s2.x, v * s2.y, v * s2.z, v * s2.w);
    red_add_v4(zp + 12, v * s3.x, v * s3.y, v * s3.z, v * s3.w);
}

// ---------------------------------------------------------------------------
// Kernel 6: gather with smem state quarter-slice, balanced.
// 128 blocks x 64 rows, 1024 threads (32 warps). Warp owns rows w and w+32.
// Per quarter: stage 128 KB slice, drain segments via conflict-free LDS.
__global__ void __launch_bounds__(1024) k_gather(const float* __restrict__ state,
                                                 float* __restrict__ out) {
    extern __shared__ float sst[];                 // QROWS*BATCH floats
    int tid  = threadIdx.x;
    int w    = tid >> 5;
    int lane = tid & 31;
    int half = lane >> 4;
    int b    = lane & 15;
    int r0   = blockIdx.x * GROWS + w;             // first owned row
    int r1   = r0 + 32;                            // second owned row

    float a0h = 0.0f, a1h = 0.0f;                  // acc for row0, row1 (this half)

#pragma unroll 1
    for (int q = 0; q < NQ; q++) {
        const float4* src = reinterpret_cast<const float4*>(g_state_T + q * QROWS * BATCH);
        float4* dst = reinterpret_cast<float4*>(sst);
#pragma unroll
        for (int k = 0; k < 8; k++)
            dst[tid + k * 1024] = src[tid + k * 1024];
        __syncthreads();

        int cbase16 = (q << 11) * BATCH;
#pragma unroll 1
        for (int rr = 0; rr < 2; rr++) {
            int r = rr ? r1 : r0;
            int bin = (r << 2) | q;
            int n = min((int)g_total[bin], QCAP);
            const float2* __restrict__ seg = g_bucket + (size_t)bin * QCAP;
            float acc = 0.0f;
            int j = half;
            for (; j + 6 < n; j += 8) {
                float2 e0 = seg[j];
                float2 e1 = seg[j + 2];
                float2 e2 = seg[j + 4];
                float2 e3 = seg[j + 6];
                float s0 = sst[__float_as_int(e0.y) * BATCH - cbase16 + b];
                float s1 = sst[__float_as_int(e1.y) * BATCH - cbase16 + b];
                float s2 = sst[__float_as_int(e2.y) * BATCH - cbase16 + b];
                float s3 = sst[__float_as_int(e3.y) * BATCH - cbase16 + b];
                acc = fmaf(e0.x, s0, acc);
                acc = fmaf(e1.x, s1, acc);
                acc = fmaf(e2.x, s2, acc);
                acc = fmaf(e3.x, s3, acc);
            }
            for (; j < n; j += 2) {
                float2 e0 = seg[j];
                acc = fmaf(e0.x, sst[__float_as_int(e0.y) * BATCH - cbase16 + b], acc);
            }
            if (rr) a1h += acc; else a0h += acc;
        }
        __syncthreads();                            // before slice overwrite
    }

    float a0 = a0h + __shfl_xor_sync(0xffffffffu, a0h, 16);
    float a1 = a1h + __shfl_xor_sync(0xffffffffu, a1h, 16);

    if (lane < BATCH) {
        float z0 = a0 + g_z[r0 * BATCH + lane];
        float s0 = state[lane * N_RES + r0];
        out[lane * N_RES + r0] = (1.0f - LEAK) * s0 + LEAK * erff(z0);
        float z1 = a1 + g_z[r1 * BATCH + lane];
        float s1 = state[lane * N_RES + r1];
        out[lane * N_RES + r1] = (1.0f - LEAK) * s1 + LEAK * erff(z1);
    }
}

// ---------------------------------------------------------------------------
extern "C" void kernel_launch(void* const* d_in, const int* in_sizes, int n_in,
                              void* d_out, int out_size) {
    const float* state    = (const float*)d_in[0];
    const float* x        = (const float*)d_in[1];
    const float* res_vals = (const float*)d_in[2];
    const int*   res_rows = (const int*)  d_in[3];
    const int*   res_cols = (const int*)  d_in[4];
    const float* res_bias = (const float*)d_in[5];
    const float* in_vals  = (const float*)d_in[6];
    const int*   in_rows  = (const int*)  d_in[7];
    const int*   in_cols  = (const int*)  d_in[8];
    const float* in_bias  = (const float*)d_in[9];
    float* out = (float*)d_out;

    int res_nnz = in_sizes[2];
    int in_nnz  = in_sizes[6];
    int csz = ((res_nnz + NCH - 1) / NCH + 3) & ~3;   // chunk size, multiple of 4

    static int smem_set = 0;
    if (!smem_set) {
        cudaFuncSetAttribute(k_hist,   cudaFuncAttributeMaxDynamicSharedMemorySize, SMEM_128K);
        cudaFuncSetAttribute(k_place,  cudaFuncAttributeMaxDynamicSharedMemorySize, SMEM_128K);
        cudaFuncSetAttribute(k_gather, cudaFuncAttributeMaxDynamicSharedMemorySize, GATHER_SMEM);
        smem_set = 1;
    }

    // Order: launch #4 = k_place (ncu capture slot).
    k_init<<<(N_RES * BATCH + 255) / 256, 256>>>(state, x, res_bias, in_bias);

    k_hist<<<NCH, 1024, SMEM_128K>>>(res_rows, res_cols, res_nnz, csz);

    k_scan<<<NBIN / 1024, 1024>>>();

    k_place<<<NCH, 1024, SMEM_128K>>>(res_vals, res_rows, res_cols, res_nnz, csz);

    k_in_spmm<<<(in_nnz + 255) / 256, 256>>>(in_vals, in_rows, in_cols, in_nnz);

    k_gather<<<N_RES / GROWS, 1024, GATHER_SMEM>>>(state, out);
}

// round 8
// speedup vs baseline: 1.1111x; 1.1111x over previous
#include <cuda_runtime.h>
#include <math.h>

#define N_RES  8192
#define N_IN   128
#define BATCH  16
#define LEAK   0.9f
#define NQ     4
#define NBIN   (N_RES * NQ)          // 32768 bins, bin = q*8192 + r
#define NCH    152                   // stream chunks = SM count
#define NNZ_MAX 6710886              // dataset RES_NNZ (fixed)
#define HIST_SMEM (NBIN * (int)sizeof(unsigned))     // 128 KB
#define PLACE_SMEM ((NBIN / 2) * (int)sizeof(unsigned))  // 64 KB

// ---------------------------------------------------------------------------
// Scratch (allocation-free __device__ globals)
__device__ __align__(16) float g_z[N_RES * BATCH];
__device__ __align__(16) float g_state_T[N_RES * BATCH];    // [row][batch]
__device__ __align__(16) float g_x_T[N_IN * BATCH];
__device__ __align__(16) unsigned short g_H[(size_t)NCH * NBIN]; // counts -> in-place per-bin prefix (u16)
__device__ unsigned g_total[NBIN];
__device__ unsigned g_base[NBIN + 1];                       // global exclusive base per bin
__device__ __align__(16) float2 g_bucket[NNZ_MAX + 8];      // 54 MB compact sorted entries

__device__ __forceinline__ void red_add_v4(float* p, float a, float b, float c, float d) {
    asm volatile("red.global.add.v4.f32 [%0], {%1,%2,%3,%4};"
                 :: "l"(p), "f"(a), "f"(b), "f"(c), "f"(d) : "memory");
}
__device__ __forceinline__ float2 ldcs_f2(const float2* p) {
    float2 r;
    asm volatile("ld.global.cs.v2.f32 {%0,%1}, [%2];" : "=f"(r.x), "=f"(r.y) : "l"(p));
    return r;
}

// ---------------------------------------------------------------------------
// Kernel: per-chunk histogram over bins (smem atomics), u16 output.
__global__ void __launch_bounds__(1024) k_hist(const int* __restrict__ rows,
                                               const int* __restrict__ cols,
                                               int nnz, int csz) {
    extern __shared__ unsigned cnt[];               // NBIN u32
    int tid = threadIdx.x, ch = blockIdx.x;
    for (int b = tid; b < NBIN; b += 1024) cnt[b] = 0;
    __syncthreads();

    int start = ch * csz, end = min(nnz, start + csz);
    for (int i = start + tid * 4; i < end; i += 4096) {
        if (i + 4 <= end) {
            int4 r4 = __ldcs((const int4*)(rows + i));
            int4 c4 = __ldcs((const int4*)(cols + i));
            atomicAdd(&cnt[((c4.x >> 11) << 13) | r4.x], 1u);
            atomicAdd(&cnt[((c4.y >> 11) << 13) | r4.y], 1u);
            atomicAdd(&cnt[((c4.z >> 11) << 13) | r4.z], 1u);
            atomicAdd(&cnt[((c4.w >> 11) << 13) | r4.w], 1u);
        } else {
            for (int k = i; k < end; k++)
                atomicAdd(&cnt[((cols[k] >> 11) << 13) | rows[k]], 1u);
        }
    }
    __syncthreads();
    unsigned short* H = g_H + (size_t)ch * NBIN;
    for (int b = tid * 2; b < NBIN; b += 2048)
        *(ushort2*)(H + b) = make_ushort2((unsigned short)cnt[b],
                                          (unsigned short)cnt[b + 1]);
}

// ---------------------------------------------------------------------------
// Kernel: per-bin exclusive prefix over chunks, IN-PLACE on g_H; totals out.
__global__ void __launch_bounds__(1024) k_scan() {
    int bin = blockIdx.x * 1024 + threadIdx.x;
    unsigned run = 0;
#pragma unroll 8
    for (int ch = 0; ch < NCH; ch++) {
        size_t idx = (size_t)ch * NBIN + bin;
        unsigned v = g_H[idx];
        g_H[idx] = (unsigned short)run;
        run += v;
    }
    g_total[bin] = run;
}

// ---------------------------------------------------------------------------
// Kernel: global exclusive scan of bin totals -> g_base (single block).
__global__ void __launch_bounds__(1024) k_base() {
    __shared__ unsigned ssum[1024];
    int tid = threadIdx.x;
    int b0 = tid * (NBIN / 1024);                    // 32 bins per thread
    unsigned local = 0;
    for (int k = 0; k < NBIN / 1024; k++) local += g_total[b0 + k];
    ssum[tid] = local;
    __syncthreads();
    for (int off = 1; off < 1024; off <<= 1) {
        unsigned v = (tid >= off) ? ssum[tid - off] : 0u;
        __syncthreads();
        ssum[tid] += v;
        __syncthreads();
    }
    unsigned run = ssum[tid] - local;                // exclusive block offset
    for (int k = 0; k < NBIN / 1024; k++) {
        unsigned t = g_total[b0 + k];
        g_base[b0 + k] = run;
        run += t;
    }
    if (tid == 1023) g_base[NBIN] = run;
}

// ---------------------------------------------------------------------------
// Kernel: place entries into compact CSR segments. No global atomics.
// 2 blocks per chunk; each owns half the bins (64 KB smem cursors).
__global__ void __launch_bounds__(1024, 2) k_place(const float* __restrict__ vals,
                                                   const int*   __restrict__ rows,
                                                   const int*   __restrict__ cols,
                                                   int nnz, int csz) {
    extern __shared__ unsigned cur[];               // NBIN/2 u32
    int tid  = threadIdx.x;
    int ch   = blockIdx.x >> 1;
    int half = blockIdx.x & 1;
    int bb   = half << 14;                          // first bin of this half
    const unsigned short* Hp = g_H + (size_t)ch * NBIN;
    for (int lb = tid; lb < NBIN / 2; lb += 1024)
        cur[lb] = g_base[bb + lb] + (unsigned)Hp[bb + lb];
    __syncthreads();

    int start = ch * csz, end = min(nnz, start + csz);
    for (int i = start + tid * 4; i < end; i += 4096) {
        if (i + 4 <= end) {
            int4   r4 = __ldcs((const int4*)(rows + i));
            int4   c4 = __ldcs((const int4*)(cols + i));
            float4 v4 = __ldcs((const float4*)(vals + i));
            int bin; unsigned p;
            bin = ((c4.x >> 11) << 13) | r4.x;
            if ((bin >> 14) == half) { p = atomicAdd(&cur[bin & 16383], 1u);
                g_bucket[p] = make_float2(v4.x, __int_as_float(c4.x)); }
            bin = ((c4.y >> 11) << 13) | r4.y;
            if ((bin >> 14) == half) { p = atomicAdd(&cur[bin & 16383], 1u);
                g_bucket[p] = make_float2(v4.y, __int_as_float(c4.y)); }
            bin = ((c4.z >> 11) << 13) | r4.z;
            if ((bin >> 14) == half) { p = atomicAdd(&cur[bin & 16383], 1u);
                g_bucket[p] = make_float2(v4.z, __int_as_float(c4.z)); }
            bin = ((c4.w >> 11) << 13) | r4.w;
            if ((bin >> 14) == half) { p = atomicAdd(&cur[bin & 16383], 1u);
                g_bucket[p] = make_float2(v4.w, __int_as_float(c4.w)); }
        } else {
            for (int k = i; k < end; k++) {
                int bin = ((cols[k] >> 11) << 13) | rows[k];
                if ((bin >> 14) == half) {
                    unsigned p = atomicAdd(&cur[bin & 16383], 1u);
                    g_bucket[p] = make_float2(vals[k], __int_as_float(cols[k]));
                }
            }
        }
    }
}

// ---------------------------------------------------------------------------
// Kernel: init z with biases, transpose state and x.
__global__ void k_init(const float* __restrict__ state,
                       const float* __restrict__ x,
                       const float* __restrict__ res_bias,
                       const float* __restrict__ in_bias) {
    int i = blockIdx.x * blockDim.x + threadIdx.x;
    if (i < N_RES * BATCH) {
        int r = i >> 4;
        int b = i & (BATCH - 1);
        g_z[i]       = res_bias[r] + in_bias[r];
        g_state_T[i] = state[b * N_RES + r];
    }
    if (i < N_IN * BATCH) {
        int r = i >> 4;
        int b = i & (BATCH - 1);
        g_x_T[i] = x[b * N_IN + r];
    }
}

// ---------------------------------------------------------------------------
// Kernel: input SpMM (small).
__global__ void k_in_spmm(const float* __restrict__ vals,
                          const int*   __restrict__ rows,
                          const int*   __restrict__ cols,
                          int nnz) {
    int i = blockIdx.x * blockDim.x + threadIdx.x;
    if (i >= nnz) return;
    float v = vals[i];
    int r = rows[i];
    int c = cols[i];
    const float4* s = reinterpret_cast<const float4*>(g_x_T + c * BATCH);
    float4 s0 = s[0], s1 = s[1], s2 = s[2], s3 = s[3];
    float* zp = g_z + r * BATCH;
    red_add_v4(zp + 0,  v * s0.x, v * s0.y, v * s0.z, v * s0.w);
    red_add_v4(zp + 4,  v * s1.x, v * s1.y, v * s1.z, v * s1.w);
    red_add_v4(zp + 8,  v * s2.x, v * s2.y, v * s2.z, v * s2.w);
    red_add_v4(zp + 12, v * s3.x, v * s3.y, v * s3.z, v * s3.w);
}

// ---------------------------------------------------------------------------
// Kernel: gather, R3-style (high occupancy, no barriers) + sw pipelining.
// One warp per row; half-warp = one entry; lane&15 = batch.
__global__ void __launch_bounds__(256) k_gather(const float* __restrict__ state,
                                                float* __restrict__ out) {
    int warp_id = (blockIdx.x * 256 + threadIdx.x) >> 5;
    if (warp_id >= N_RES) return;
    int r    = warp_id;
    int lane = threadIdx.x & 31;
    int half = lane >> 4;
    int b    = lane & 15;

    float acc0 = 0.0f, acc1 = 0.0f;
#pragma unroll 1
    for (int q = 0; q < NQ; q++) {
        int bin = (q << 13) | r;
        unsigned beg = g_base[bin];
        int n = (int)(g_base[bin + 1] - beg);
        const float2* __restrict__ seg = g_bucket + beg;

        int j = half;
        if (j + 14 < n) {
            // software pipeline: current 4 entries + prefetch next 4
            float2 c0 = ldcs_f2(seg + j);
            float2 c1 = ldcs_f2(seg + j + 2);
            float2 c2 = ldcs_f2(seg + j + 4);
            float2 c3 = ldcs_f2(seg + j + 6);
            for (; j + 14 < n; j += 8) {
                float2 n0 = ldcs_f2(seg + j + 8);
                float2 n1 = ldcs_f2(seg + j + 10);
                float2 n2 = ldcs_f2(seg + j + 12);
                float2 n3 = ldcs_f2(seg + j + 14);
                float s0 = __ldg(&g_state_T[__float_as_int(c0.y) * BATCH + b]);
                float s1 = __ldg(&g_state_T[__float_as_int(c1.y) * BATCH + b]);
                float s2 = __ldg(&g_state_T[__float_as_int(c2.y) * BATCH + b]);
                float s3 = __ldg(&g_state_T[__float_as_int(c3.y) * BATCH + b]);
                acc0 = fmaf(c0.x, s0, acc0);
                acc1 = fmaf(c1.x, s1, acc1);
                acc0 = fmaf(c2.x, s2, acc0);
                acc1 = fmaf(c3.x, s3, acc1);
                c0 = n0; c1 = n1; c2 = n2; c3 = n3;
            }
            // drain the pipelined 4
            acc0 = fmaf(c0.x, __ldg(&g_state_T[__float_as_int(c0.y) * BATCH + b]), acc0);
            acc1 = fmaf(c1.x, __ldg(&g_state_T[__float_as_int(c1.y) * BATCH + b]), acc1);
            acc0 = fmaf(c2.x, __ldg(&g_state_T[__float_as_int(c2.y) * BATCH + b]), acc0);
            acc1 = fmaf(c3.x, __ldg(&g_state_T[__float_as_int(c3.y) * BATCH + b]), acc1);
            j += 8;
        }
        for (; j < n; j += 2) {
            float2 e = ldcs_f2(seg + j);
            acc0 = fmaf(e.x, __ldg(&g_state_T[__float_as_int(e.y) * BATCH + b]), acc0);
        }
    }
    float acc = acc0 + acc1;
    acc += __shfl_xor_sync(0xffffffffu, acc, 16);

    if (lane < BATCH) {
        float z = acc + g_z[r * BATCH + lane];
        float s = state[lane * N_RES + r];
        out[lane * N_RES + r] = (1.0f - LEAK) * s + LEAK * erff(z);
    }
}

// ---------------------------------------------------------------------------
extern "C" void kernel_launch(void* const* d_in, const int* in_sizes, int n_in,
                              void* d_out, int out_size) {
    const float* state    = (const float*)d_in[0];
    const float* x        = (const float*)d_in[1];
    const float* res_vals = (const float*)d_in[2];
    const int*   res_rows = (const int*)  d_in[3];
    const int*   res_cols = (const int*)  d_in[4];
    const float* res_bias = (const float*)d_in[5];
    const float* in_vals  = (const float*)d_in[6];
    const int*   in_rows  = (const int*)  d_in[7];
    const int*   in_cols  = (const int*)  d_in[8];
    const float* in_bias  = (const float*)d_in[9];
    float* out = (float*)d_out;

    int res_nnz = in_sizes[2];
    int in_nnz  = in_sizes[6];
    int csz = ((res_nnz + NCH - 1) / NCH + 3) & ~3;

    static int smem_set = 0;
    if (!smem_set) {
        cudaFuncSetAttribute(k_hist,  cudaFuncAttributeMaxDynamicSharedMemorySize, HIST_SMEM);
        cudaFuncSetAttribute(k_place, cudaFuncAttributeMaxDynamicSharedMemorySize, PLACE_SMEM);
        smem_set = 1;
    }

    // Launch order: slot 4 (ncu capture) = k_place.
    k_hist<<<NCH, 1024, HIST_SMEM>>>(res_rows, res_cols, res_nnz, csz);

    k_scan<<<NBIN / 1024, 1024>>>();

    k_base<<<1, 1024>>>();

    k_place<<<2 * NCH, 1024, PLACE_SMEM>>>(res_vals, res_rows, res_cols, res_nnz, csz);

    k_init<<<(N_RES * BATCH + 255) / 256, 256>>>(state, x, res_bias, in_bias);

    k_in_spmm<<<(in_nnz + 255) / 256, 256>>>(in_vals, in_rows, in_cols, in_nnz);

    k_gather<<<N_RES / 8, 256>>>(state, out);
}

// round 9
// speedup vs baseline: 1.1425x; 1.0282x over previous
#include <cuda_runtime.h>
#include <math.h>

#define N_RES  8192
#define N_IN   128
#define BATCH  16
#define LEAK   0.9f

#define NCB     256                 // coarse bins (32 rows each)
#define CCAP    28672               // per-bin capacity (Poisson 26214, +15 sigma)
#define DEPTH_C 64                  // coarse staging depth (mean 32/round)
#define NCH     152                 // coarse stream chunks (1/SM)
#define TC      8192                // entries per coarse round (1024 thr x 8)

#define DEPTH_F 192                 // fuse staging depth per row (mean 128/round)
#define TF      4096                // entries per fuse round (512 thr x 8)

#define COARSE_SMEM (NCB * DEPTH_C * (int)sizeof(float2))   // 128 KB
#define FUSE_SMEM   (32 * DEPTH_F * (int)sizeof(float2))    // 48 KB

// ---------------------------------------------------------------------------
// Scratch (allocation-free __device__ globals)
__device__ __align__(16) float g_z[N_RES * BATCH];          // bias + input-spmm acc, [row][16]
__device__ __align__(16) float g_state_T[N_RES * BATCH];    // [row][batch]
__device__ __align__(16) float g_x_T[N_IN * BATCH];
__device__ unsigned g_ccur[NCB];                            // coarse bin cursors
__device__ __align__(16) float2 g_cbucket[(size_t)NCB * CCAP];  // 58.7 MB coarse bucket

__device__ __forceinline__ void red_add_v4(float* p, float a, float b, float c, float d) {
    asm volatile("red.global.add.v4.f32 [%0], {%1,%2,%3,%4};"
                 :: "l"(p), "f"(a), "f"(b), "f"(c), "f"(d) : "memory");
}

// ---------------------------------------------------------------------------
// Kernel 1: init z with biases, zero coarse cursors, transpose state and x.
__global__ void k_init(const float* __restrict__ state,
                       const float* __restrict__ x,
                       const float* __restrict__ res_bias,
                       const float* __restrict__ in_bias) {
    int i = blockIdx.x * blockDim.x + threadIdx.x;
    if (i < N_RES * BATCH) {
        int r = i >> 4;
        int b = i & (BATCH - 1);
        g_z[i]       = res_bias[r] + in_bias[r];
        g_state_T[i] = state[b * N_RES + r];
    }
    if (i < N_IN * BATCH) {
        int r = i >> 4;
        int b = i & (BATCH - 1);
        g_x_T[i] = x[b * N_IN + r];
    }
    if (i < NCB) g_ccur[i] = 0;
}

// ---------------------------------------------------------------------------
// Kernel 2: input SpMM (small: ~105K entries).
__global__ void k_in_spmm(const float* __restrict__ vals,
                          const int*   __restrict__ rows,
                          const int*   __restrict__ cols,
                          int nnz) {
    int i = blockIdx.x * blockDim.x + threadIdx.x;
    if (i >= nnz) return;
    float v = vals[i];
    int r = rows[i];
    int c = cols[i];
    const float4* s = reinterpret_cast<const float4*>(g_x_T + c * BATCH);
    float4 s0 = s[0], s1 = s[1], s2 = s[2], s3 = s[3];
    float* zp = g_z + r * BATCH;
    red_add_v4(zp + 0,  v * s0.x, v * s0.y, v * s0.z, v * s0.w);
    red_add_v4(zp + 4,  v * s1.x, v * s1.y, v * s1.z, v * s1.w);
    red_add_v4(zp + 8,  v * s2.x, v * s2.y, v * s2.z, v * s2.w);
    red_add_v4(zp + 12, v * s3.x, v * s3.y, v * s3.z, v * s3.w);
}

// ---------------------------------------------------------------------------
// Kernel 3: coarse partition by row-block (r>>5) with smem staging and
// COALESCED flush — no fine-scattered global stores anywhere.
__global__ void __launch_bounds__(1024) k_coarse(const float* __restrict__ vals,
                                                 const int*   __restrict__ rows,
                                                 const int*   __restrict__ cols,
                                                 int nnz, int csz) {
    extern __shared__ float2 sbuf[];             // NCB * DEPTH_C
    __shared__ unsigned scnt[NCB];
    int tid  = threadIdx.x;
    int w    = tid >> 5;
    int lane = tid & 31;
    int start = blockIdx.x * csz;
    int end   = min(nnz, start + csz);

    for (int base = start; base < end; base += TC) {
        if (tid < NCB) scnt[tid] = 0;
        __syncthreads();

        int i0 = base + tid * 8;
        if (base + TC <= end) {
            float4 v0 = *(const float4*)(vals + i0);
            float4 v1 = *(const float4*)(vals + i0 + 4);
            int4   r0 = *(const int4*)(rows + i0);
            int4   r1 = *(const int4*)(rows + i0 + 4);
            int4   c0 = *(const int4*)(cols + i0);
            int4   c1 = *(const int4*)(cols + i0 + 4);
            float vv[8] = {v0.x, v0.y, v0.z, v0.w, v1.x, v1.y, v1.z, v1.w};
            int   rr[8] = {r0.x, r0.y, r0.z, r0.w, r1.x, r1.y, r1.z, r1.w};
            int   cc[8] = {c0.x, c0.y, c0.z, c0.w, c1.x, c1.y, c1.z, c1.w};
#pragma unroll
            for (int k = 0; k < 8; k++) {
                int bin = rr[k] >> 5;
                unsigned pos = atomicAdd(&scnt[bin], 1u);
                float2 e = make_float2(vv[k],
                    __int_as_float(cc[k] | ((rr[k] & 31) << 13)));
                if (pos < DEPTH_C) sbuf[bin * DEPTH_C + pos] = e;
                else {                                   // ~never: direct path
                    unsigned p = atomicAdd(&g_ccur[bin], 1u);
                    if (p < CCAP) g_cbucket[(size_t)bin * CCAP + p] = e;
                }
            }
        } else {
            for (int k = 0; k < 8; k++) {
                int i = i0 + k;
                if (i < end) {
                    int r = rows[i], c = cols[i];
                    int bin = r >> 5;
                    unsigned pos = atomicAdd(&scnt[bin], 1u);
                    float2 e = make_float2(vals[i],
                        __int_as_float(c | ((r & 31) << 13)));
                    if (pos < DEPTH_C) sbuf[bin * DEPTH_C + pos] = e;
                    else {
                        unsigned p = atomicAdd(&g_ccur[bin], 1u);
                        if (p < CCAP) g_cbucket[(size_t)bin * CCAP + p] = e;
                    }
                }
            }
        }
        __syncthreads();

        // Flush: 32 warps x 8 bins, one cursor atomic per bin, coalesced copies.
        for (int b = w * 8; b < w * 8 + 8; b++) {
            int cnt = min(scnt[b], (unsigned)DEPTH_C);
            if (cnt == 0) continue;
            unsigned gb = 0;
            if (lane == 0) gb = atomicAdd(&g_ccur[b], (unsigned)cnt);
            gb = __shfl_sync(0xffffffffu, gb, 0);
            size_t dst = (size_t)b * CCAP + gb;
            if (lane < cnt)
                g_cbucket[dst + lane] = sbuf[b * DEPTH_C + lane];
            if (cnt > 32 && lane + 32 < cnt)
                g_cbucket[dst + lane + 32] = sbuf[b * DEPTH_C + lane + 32];
        }
        __syncthreads();
    }
}

// ---------------------------------------------------------------------------
// Kernel 4 (ncu slot): fused refine + gather + epilogue.
// Block = one coarse bin (32 rows), 512 threads, 4 blocks/SM.
// Per round: stream TF entries coalesced, stage by row-in-bin in smem,
// then 16 warps drain 2 rows each into register accumulators.
__global__ void __launch_bounds__(512, 4) k_fuse(const float* __restrict__ state,
                                                 float* __restrict__ out) {
    extern __shared__ float2 stg[];              // 32 * DEPTH_F
    __shared__ unsigned scnt[32];
    int tid  = threadIdx.x;
    int w    = tid >> 5;                         // warp 0..15 -> rows 2w, 2w+1
    int lane = tid & 31;
    int half = lane >> 4;
    int b    = lane & 15;
    int cb   = blockIdx.x;

    int cnt = min(g_ccur[cb], (unsigned)CCAP);
    const float2* __restrict__ src = g_cbucket + (size_t)cb * CCAP;

    float acc0 = 0.0f, acc1 = 0.0f;              // rows cb*32+2w, +2w+1

    for (int base = 0; base < cnt; base += TF) {
        if (tid < 32) scnt[tid] = 0;
        __syncthreads();

        int n = min(TF, cnt - base);
        for (int k = tid; k < n; k += 512) {     // coalesced stream
            float2 e = src[base + k];
            int bits = __float_as_int(e.y);
            int rl = (bits >> 13) & 31;
            unsigned pos = atomicAdd(&scnt[rl], 1u);
            if (pos < DEPTH_F) {
                stg[rl * DEPTH_F + pos] = e;
            } else {                             // ~never: direct z accumulation
                int c = bits & 8191;
                float v = e.x;
                const float4* s4 = reinterpret_cast<const float4*>(g_state_T + c * BATCH);
                float4 s0 = s4[0], s1 = s4[1], s2 = s4[2], s3 = s4[3];
                float* zp = g_z + ((cb << 5) | rl) * BATCH;
                red_add_v4(zp + 0,  v * s0.x, v * s0.y, v * s0.z, v * s0.w);
                red_add_v4(zp + 4,  v * s1.x, v * s1.y, v * s1.z, v * s1.w);
                red_add_v4(zp + 8,  v * s2.x, v * s2.y, v * s2.z, v * s2.w);
                red_add_v4(zp + 12, v * s3.x, v * s3.y, v * s3.z, v * s3.w);
                __threadfence();
            }
        }
        __syncthreads();

        // Drain: warp w handles rows 2w and 2w+1; half-warp = one entry.
#pragma unroll
        for (int rr = 0; rr < 2; rr++) {
            int rl = (w << 1) | rr;
            int m = min(scnt[rl], (unsigned)DEPTH_F);
            const float2* row = stg + rl * DEPTH_F;
            float acc = 0.0f;
            int j = half;
            for (; j + 6 < m; j += 8) {
                float2 e0 = row[j];
                float2 e1 = row[j + 2];
                float2 e2 = row[j + 4];
                float2 e3 = row[j + 6];
                float s0 = g_state_T[(__float_as_int(e0.y) & 8191) * BATCH + b];
                float s1 = g_state_T[(__float_as_int(e1.y) & 8191) * BATCH + b];
                float s2 = g_state_T[(__float_as_int(e2.y) & 8191) * BATCH + b];
                float s3 = g_state_T[(__float_as_int(e3.y) & 8191) * BATCH + b];
                acc = fmaf(e0.x, s0, acc);
                acc = fmaf(e1.x, s1, acc);
                acc = fmaf(e2.x, s2, acc);
                acc = fmaf(e3.x, s3, acc);
            }
            for (; j < m; j += 2) {
                float2 e = row[j];
                acc = fmaf(e.x, g_state_T[(__float_as_int(e.y) & 8191) * BATCH + b], acc);
            }
            if (rr) acc1 += acc; else acc0 += acc;
        }
        __syncthreads();
    }

    // Combine half-warp partials; fused epilogue.
    acc0 += __shfl_xor_sync(0xffffffffu, acc0, 16);
    acc1 += __shfl_xor_sync(0xffffffffu, acc1, 16);

    if (lane < BATCH) {
        int r0 = (cb << 5) | (w << 1);
        int r1 = r0 + 1;
        float z0 = acc0 + g_z[r0 * BATCH + lane];
        float s0 = state[lane * N_RES + r0];
        out[lane * N_RES + r0] = (1.0f - LEAK) * s0 + LEAK * erff(z0);
        float z1 = acc1 + g_z[r1 * BATCH + lane];
        float s1 = state[lane * N_RES + r1];
        out[lane * N_RES + r1] = (1.0f - LEAK) * s1 + LEAK * erff(z1);
    }
}

// ---------------------------------------------------------------------------
extern "C" void kernel_launch(void* const* d_in, const int* in_sizes, int n_in,
                              void* d_out, int out_size) {
    const float* state    = (const float*)d_in[0];
    const float* x        = (const float*)d_in[1];
    const float* res_vals = (const float*)d_in[2];
    const int*   res_rows = (const int*)  d_in[3];
    const int*   res_cols = (const int*)  d_in[4];
    const float* res_bias = (const float*)d_in[5];
    const float* in_vals  = (const float*)d_in[6];
    const int*   in_rows  = (const int*)  d_in[7];
    const int*   in_cols  = (const int*)  d_in[8];
    const float* in_bias  = (const float*)d_in[9];
    float* out = (float*)d_out;

    int res_nnz = in_sizes[2];
    int in_nnz  = in_sizes[6];
    int csz = ((res_nnz + NCH - 1) / NCH + 7) & ~7;   // chunk size, multiple of 8

    static int smem_set = 0;
    if (!smem_set) {
        cudaFuncSetAttribute(k_coarse, cudaFuncAttributeMaxDynamicSharedMemorySize, COARSE_SMEM);
        cudaFuncSetAttribute(k_fuse,   cudaFuncAttributeMaxDynamicSharedMemorySize, FUSE_SMEM);
        smem_set = 1;
    }

    // Launch order: slot 4 (ncu capture) = k_fuse.
    k_init<<<(N_RES * BATCH + 255) / 256, 256>>>(state, x, res_bias, in_bias);

    k_in_spmm<<<(in_nnz + 255) / 256, 256>>>(in_vals, in_rows, in_cols, in_nnz);

    k_coarse<<<NCH, 1024, COARSE_SMEM>>>(res_vals, res_rows, res_cols, res_nnz, csz);

    k_fuse<<<NCB, 512, FUSE_SMEM>>>(state, out);
}

// round 10
// speedup vs baseline: 1.4995x; 1.3124x over previous
#include <cuda_runtime.h>
#include <math.h>

#define N_RES  8192
#define N_IN   128
#define BATCH  16
#define LEAK   0.9f

#define NCB     256                 // coarse bins (32 rows each)
#define CCAP    28672               // per-bin capacity (Poisson 26214, +15 sigma)
#define DEPTH_C 64                  // coarse staging depth (mean 32/round)
#define NCH     152                 // coarse stream chunks (1/SM)
#define TC      8192                // entries per coarse round (1024 thr x 8)

#define DEPTH_F 192                 // fuse staging depth per row (mean 128/round)
#define TF      4096                // entries per fuse round (512 thr x 8)

#define COARSE_SMEM (NCB * DEPTH_C * (int)sizeof(float2))   // 128 KB
#define FUSE_SMEM   (32 * DEPTH_F * (int)sizeof(float2))    // 48 KB

// ---------------------------------------------------------------------------
// Scratch (allocation-free __device__ globals)
__device__ __align__(16) float g_z[N_RES * BATCH];          // bias + input-spmm acc
__device__ __align__(16) float g_state_T[N_RES * BATCH];    // [row][batch]
__device__ __align__(16) float g_x_T[N_IN * BATCH];
__device__ unsigned g_ccur[NCB];
__device__ __align__(16) float2 g_cbucket[(size_t)NCB * CCAP];  // 58.7 MB

__device__ __forceinline__ void red_add_v4(float* p, float a, float b, float c, float d) {
    asm volatile("red.global.add.v4.f32 [%0], {%1,%2,%3,%4};"
                 :: "l"(p), "f"(a), "f"(b), "f"(c), "f"(d) : "memory");
}

// ---------------------------------------------------------------------------
// Kernel 1: init z with biases, zero coarse cursors, transpose state and x.
__global__ void k_init(const float* __restrict__ state,
                       const float* __restrict__ x,
                       const float* __restrict__ res_bias,
                       const float* __restrict__ in_bias) {
    int i = blockIdx.x * blockDim.x + threadIdx.x;
    if (i < N_RES * BATCH) {
        int r = i >> 4;
        int b = i & (BATCH - 1);
        g_z[i]       = res_bias[r] + in_bias[r];
        g_state_T[i] = state[b * N_RES + r];
    }
    if (i < N_IN * BATCH) {
        int r = i >> 4;
        int b = i & (BATCH - 1);
        g_x_T[i] = x[b * N_IN + r];
    }
    if (i < NCB) g_ccur[i] = 0;
}

// ---------------------------------------------------------------------------
// Kernel 2: input SpMM (small: ~105K entries).
__global__ void k_in_spmm(const float* __restrict__ vals,
                          const int*   __restrict__ rows,
                          const int*   __restrict__ cols,
                          int nnz) {
    int i = blockIdx.x * blockDim.x + threadIdx.x;
    if (i >= nnz) return;
    float v = vals[i];
    int r = rows[i];
    int c = cols[i];
    const float4* s = reinterpret_cast<const float4*>(g_x_T + c * BATCH);
    float4 s0 = s[0], s1 = s[1], s2 = s[2], s3 = s[3];
    float* zp = g_z + r * BATCH;
    red_add_v4(zp + 0,  v * s0.x, v * s0.y, v * s0.z, v * s0.w);
    red_add_v4(zp + 4,  v * s1.x, v * s1.y, v * s1.z, v * s1.w);
    red_add_v4(zp + 8,  v * s2.x, v * s2.y, v * s2.z, v * s2.w);
    red_add_v4(zp + 12, v * s3.x, v * s3.y, v * s3.z, v * s3.w);
}

// ---------------------------------------------------------------------------
// Kernel 3: coarse partition by row-block (r>>5), smem staging, coalesced
// flush with PARALLEL cursor reservation (1 round-trip per round, not 8/warp).
__global__ void __launch_bounds__(1024) k_coarse(const float* __restrict__ vals,
                                                 const int*   __restrict__ rows,
                                                 const int*   __restrict__ cols,
                                                 int nnz, int csz) {
    extern __shared__ float2 sbuf[];             // NCB * DEPTH_C
    __shared__ unsigned scnt[NCB];
    __shared__ unsigned sbase[NCB];
    int tid  = threadIdx.x;
    int w    = tid >> 5;
    int lane = tid & 31;
    int start = blockIdx.x * csz;
    int end   = min(nnz, start + csz);

    for (int base = start; base < end; base += TC) {
        if (tid < NCB) scnt[tid] = 0;
        __syncthreads();

        int i0 = base + tid * 8;
        if (base + TC <= end) {
            float4 v0 = *(const float4*)(vals + i0);
            float4 v1 = *(const float4*)(vals + i0 + 4);
            int4   r0 = *(const int4*)(rows + i0);
            int4   r1 = *(const int4*)(rows + i0 + 4);
            int4   c0 = *(const int4*)(cols + i0);
            int4   c1 = *(const int4*)(cols + i0 + 4);
            float vv[8] = {v0.x, v0.y, v0.z, v0.w, v1.x, v1.y, v1.z, v1.w};
            int   rr[8] = {r0.x, r0.y, r0.z, r0.w, r1.x, r1.y, r1.z, r1.w};
            int   cc[8] = {c0.x, c0.y, c0.z, c0.w, c1.x, c1.y, c1.z, c1.w};
#pragma unroll
            for (int k = 0; k < 8; k++) {
                int bin = rr[k] >> 5;
                unsigned pos = atomicAdd(&scnt[bin], 1u);
                float2 e = make_float2(vv[k],
                    __int_as_float(cc[k] | ((rr[k] & 31) << 13)));
                if (pos < DEPTH_C) sbuf[bin * DEPTH_C + pos] = e;
                else {                                   // ~never
                    unsigned p = atomicAdd(&g_ccur[bin], 1u);
                    if (p < CCAP) g_cbucket[(size_t)bin * CCAP + p] = e;
                }
            }
        } else {
            for (int k = 0; k < 8; k++) {
                int i = i0 + k;
                if (i < end) {
                    int r = rows[i], c = cols[i];
                    int bin = r >> 5;
                    unsigned pos = atomicAdd(&scnt[bin], 1u);
                    float2 e = make_float2(vals[i],
                        __int_as_float(c | ((r & 31) << 13)));
                    if (pos < DEPTH_C) sbuf[bin * DEPTH_C + pos] = e;
                    else {
                        unsigned p = atomicAdd(&g_ccur[bin], 1u);
                        if (p < CCAP) g_cbucket[(size_t)bin * CCAP + p] = e;
                    }
                }
            }
        }
        __syncthreads();

        // Parallel reservation: 256 concurrent global atomics (one per bin).
        if (tid < NCB) {
            unsigned c = min(scnt[tid], (unsigned)DEPTH_C);
            sbase[tid] = c ? atomicAdd(&g_ccur[tid], c) : 0u;
        }
        __syncthreads();

        // Copy: warp w -> bins 8w..8w+7, coalesced, no atomics.
        for (int b = w * 8; b < w * 8 + 8; b++) {
            unsigned cnt = min(scnt[b], (unsigned)DEPTH_C);
            if (cnt == 0) continue;
            size_t dst = (size_t)b * CCAP + sbase[b];
            if (lane < cnt)
                g_cbucket[dst + lane] = sbuf[b * DEPTH_C + lane];
            if (cnt > 32 && lane + 32 < cnt)
                g_cbucket[dst + lane + 32] = sbuf[b * DEPTH_C + lane + 32];
        }
        __syncthreads();
    }
}

// ---------------------------------------------------------------------------
// Kernel 4 (ncu slot): fused refine + gather + epilogue, software-pipelined.
// Block = one coarse bin (32 rows), 512 threads. Next round's stream chunk is
// preloaded into registers before draining the current round.
__global__ void __launch_bounds__(512, 4) k_fuse(const float* __restrict__ state,
                                                 float* __restrict__ out) {
    extern __shared__ float2 stg[];              // 32 * DEPTH_F
    __shared__ unsigned scnt[32];
    int tid  = threadIdx.x;
    int w    = tid >> 5;
    int lane = tid & 31;
    int half = lane >> 4;
    int b    = lane & 15;
    int cb   = blockIdx.x;

    int cnt = min(g_ccur[cb], (unsigned)CCAP);
    const float2* __restrict__ src = g_cbucket + (size_t)cb * CCAP;

    float acc0 = 0.0f, acc1 = 0.0f;

    // Preload round 0.
    float2 pre[8];
    int npre = min(TF, cnt);
#pragma unroll
    for (int k = 0; k < 8; k++) {
        int idx = tid + k * 512;
        if (idx < npre) pre[k] = src[idx];
    }

    for (int base = 0; base < cnt; base += TF) {
        int n = npre;
        if (tid < 32) scnt[tid] = 0;
        __syncthreads();

        // Stage from preloaded registers.
#pragma unroll
        for (int k = 0; k < 8; k++) {
            int idx = tid + k * 512;
            if (idx < n) {
                float2 e = pre[k];
                int rl = (__float_as_int(e.y) >> 13) & 31;
                unsigned pos = atomicAdd(&scnt[rl], 1u);
                if (pos < DEPTH_F) {
                    stg[rl * DEPTH_F + pos] = e;
                } else {                         // ~never: direct z accumulation
                    int c = __float_as_int(e.y) & 8191;
                    float v = e.x;
                    const float4* s4 = reinterpret_cast<const float4*>(g_state_T + c * BATCH);
                    float4 s0 = s4[0], s1 = s4[1], s2 = s4[2], s3 = s4[3];
                    float* zp = g_z + ((cb << 5) | rl) * BATCH;
                    red_add_v4(zp + 0,  v * s0.x, v * s0.y, v * s0.z, v * s0.w);
                    red_add_v4(zp + 4,  v * s1.x, v * s1.y, v * s1.z, v * s1.w);
                    red_add_v4(zp + 8,  v * s2.x, v * s2.y, v * s2.z, v * s2.w);
                    red_add_v4(zp + 12, v * s3.x, v * s3.y, v * s3.z, v * s3.w);
                    __threadfence();
                }
            }
        }
        __syncthreads();

        // Preload NEXT round while draining this one (overlaps LDG latency).
        int nbase = base + TF;
        npre = min(TF, cnt - nbase);
#pragma unroll
        for (int k = 0; k < 8; k++) {
            int idx = tid + k * 512;
            if (idx < npre) pre[k] = src[nbase + idx];
        }

        // Drain: warp w handles rows 2w, 2w+1; half-warp = one entry.
#pragma unroll
        for (int rr = 0; rr < 2; rr++) {
            int rl = (w << 1) | rr;
            int m = min(scnt[rl], (unsigned)DEPTH_F);
            const float2* row = stg + rl * DEPTH_F;
            float acc = 0.0f;
            int j = half;
            for (; j + 6 < m; j += 8) {
                float2 e0 = row[j];
                float2 e1 = row[j + 2];
                float2 e2 = row[j + 4];
                float2 e3 = row[j + 6];
                float s0 = g_state_T[(__float_as_int(e0.y) & 8191) * BATCH + b];
                float s1 = g_state_T[(__float_as_int(e1.y) & 8191) * BATCH + b];
                float s2 = g_state_T[(__float_as_int(e2.y) & 8191) * BATCH + b];
                float s3 = g_state_T[(__float_as_int(e3.y) & 8191) * BATCH + b];
                acc = fmaf(e0.x, s0, acc);
                acc = fmaf(e1.x, s1, acc);
                acc = fmaf(e2.x, s2, acc);
                acc = fmaf(e3.x, s3, acc);
            }
            for (; j < m; j += 2) {
                float2 e = row[j];
                acc = fmaf(e.x, g_state_T[(__float_as_int(e.y) & 8191) * BATCH + b], acc);
            }
            if (rr) acc1 += acc; else acc0 += acc;
        }
        __syncthreads();
    }

    acc0 += __shfl_xor_sync(0xffffffffu, acc0, 16);
    acc1 += __shfl_xor_sync(0xffffffffu, acc1, 16);

    if (lane < BATCH) {
        int r0 = (cb << 5) | (w << 1);
        int r1 = r0 + 1;
        float z0 = acc0 + g_z[r0 * BATCH + lane];
        float s0 = state[lane * N_RES + r0];
        out[lane * N_RES + r0] = (1.0f - LEAK) * s0 + LEAK * erff(z0);
        float z1 = acc1 + g_z[r1 * BATCH + lane];
        float s1 = state[lane * N_RES + r1];
        out[lane * N_RES + r1] = (1.0f - LEAK) * s1 + LEAK * erff(z1);
    }
}

// ---------------------------------------------------------------------------
extern "C" void kernel_launch(void* const* d_in, const int* in_sizes, int n_in,
                              void* d_out, int out_size) {
    const float* state    = (const float*)d_in[0];
    const float* x        = (const float*)d_in[1];
    const float* res_vals = (const float*)d_in[2];
    const int*   res_rows = (const int*)  d_in[3];
    const int*   res_cols = (const int*)  d_in[4];
    const float* res_bias = (const float*)d_in[5];
    const float* in_vals  = (const float*)d_in[6];
    const int*   in_rows  = (const int*)  d_in[7];
    const int*   in_cols  = (const int*)  d_in[8];
    const float* in_bias  = (const float*)d_in[9];
    float* out = (float*)d_out;

    int res_nnz = in_sizes[2];
    int in_nnz  = in_sizes[6];
    int csz = ((res_nnz + NCH - 1) / NCH + 7) & ~7;

    static int smem_set = 0;
    if (!smem_set) {
        cudaFuncSetAttribute(k_coarse, cudaFuncAttributeMaxDynamicSharedMemorySize, COARSE_SMEM);
        cudaFuncSetAttribute(k_fuse,   cudaFuncAttributeMaxDynamicSharedMemorySize, FUSE_SMEM);
        smem_set = 1;
    }

    // Launch order: slot 4 (ncu capture) = k_fuse.
    k_init<<<(N_RES * BATCH + 255) / 256, 256>>>(state, x, res_bias, in_bias);

    k_in_spmm<<<(in_nnz + 255) / 256, 256>>>(in_vals, in_rows, in_cols, in_nnz);

    k_coarse<<<NCH, 1024, COARSE_SMEM>>>(res_vals, res_rows, res_cols, res_nnz, csz);

    k_fuse<<<NCB, 512, FUSE_SMEM>>>(state, out);
}

// round 11
// speedup vs baseline: 1.8247x; 1.2169x over previous
#include <cuda_runtime.h>
#include <math.h>

#define N_RES  8192
#define N_IN   128
#define BATCH  16
#define LEAK   0.9f

#define NCB     256                 // coarse bins (32 rows each)
#define CCAP    28672               // per-bin capacity (Poisson 26214, +15 sigma)
#define DEPTH_C 64                  // coarse staging depth (mean 32/round)
#define NCH     152                 // coarse stream chunks (1/SM)
#define TC      8192                // entries per coarse round (1024 thr x 8)

#define NSEG    2                   // fuse segments per coarse bin (grid = 512)
#define DEPTH_F 192                 // fuse staging depth per row per round
#define TF      4096                // entries per fuse round (512 thr x 8)

#define COARSE_SMEM (NCB * DEPTH_C * (int)sizeof(float2))   // 128 KB
#define FUSE_SMEM   (32 * DEPTH_F * (int)sizeof(float2))    // 48 KB

// ---------------------------------------------------------------------------
// Scratch (allocation-free __device__ globals)
__device__ __align__(16) float g_z[N_RES * BATCH];          // bias + input + reservoir acc
__device__ __align__(16) float g_state_T[N_RES * BATCH];    // [row][batch]
__device__ __align__(16) float g_x_T[N_IN * BATCH];
__device__ unsigned g_ccur[NCB];
__device__ __align__(16) float2 g_cbucket[(size_t)NCB * CCAP];  // 58.7 MB

__device__ __forceinline__ void red_add_v4(float* p, float a, float b, float c, float d) {
    asm volatile("red.global.add.v4.f32 [%0], {%1,%2,%3,%4};"
                 :: "l"(p), "f"(a), "f"(b), "f"(c), "f"(d) : "memory");
}
__device__ __forceinline__ void red_add_f32(float* p, float a) {
    asm volatile("red.global.add.f32 [%0], %1;" :: "l"(p), "f"(a) : "memory");
}

// ---------------------------------------------------------------------------
// Kernel 1: init z with biases, zero coarse cursors, transpose state and x.
__global__ void k_init(const float* __restrict__ state,
                       const float* __restrict__ x,
                       const float* __restrict__ res_bias,
                       const float* __restrict__ in_bias) {
    int i = blockIdx.x * blockDim.x + threadIdx.x;
    if (i < N_RES * BATCH) {
        int r = i >> 4;
        int b = i & (BATCH - 1);
        g_z[i]       = res_bias[r] + in_bias[r];
        g_state_T[i] = state[b * N_RES + r];
    }
    if (i < N_IN * BATCH) {
        int r = i >> 4;
        int b = i & (BATCH - 1);
        g_x_T[i] = x[b * N_IN + r];
    }
    if (i < NCB) g_ccur[i] = 0;
}

// ---------------------------------------------------------------------------
// Kernel 2: input SpMM (small: ~105K entries).
__global__ void k_in_spmm(const float* __restrict__ vals,
                          const int*   __restrict__ rows,
                          const int*   __restrict__ cols,
                          int nnz) {
    int i = blockIdx.x * blockDim.x + threadIdx.x;
    if (i >= nnz) return;
    float v = vals[i];
    int r = rows[i];
    int c = cols[i];
    const float4* s = reinterpret_cast<const float4*>(g_x_T + c * BATCH);
    float4 s0 = s[0], s1 = s[1], s2 = s[2], s3 = s[3];
    float* zp = g_z + r * BATCH;
    red_add_v4(zp + 0,  v * s0.x, v * s0.y, v * s0.z, v * s0.w);
    red_add_v4(zp + 4,  v * s1.x, v * s1.y, v * s1.z, v * s1.w);
    red_add_v4(zp + 8,  v * s2.x, v * s2.y, v * s2.z, v * s2.w);
    red_add_v4(zp + 12, v * s3.x, v * s3.y, v * s3.z, v * s3.w);
}

// ---------------------------------------------------------------------------
// Kernel 3: coarse partition by row-block (r>>5), smem staging, coalesced
// flush with parallel cursor reservation (proven in R10).
__global__ void __launch_bounds__(1024) k_coarse(const float* __restrict__ vals,
                                                 const int*   __restrict__ rows,
                                                 const int*   __restrict__ cols,
                                                 int nnz, int csz) {
    extern __shared__ float2 sbuf[];             // NCB * DEPTH_C
    __shared__ unsigned scnt[NCB];
    __shared__ unsigned sbase[NCB];
    int tid  = threadIdx.x;
    int w    = tid >> 5;
    int lane = tid & 31;
    int start = blockIdx.x * csz;
    int end   = min(nnz, start + csz);

    for (int base = start; base < end; base += TC) {
        if (tid < NCB) scnt[tid] = 0;
        __syncthreads();

        int i0 = base + tid * 8;
        if (base + TC <= end) {
            float4 v0 = *(const float4*)(vals + i0);
            float4 v1 = *(const float4*)(vals + i0 + 4);
            int4   r0 = *(const int4*)(rows + i0);
            int4   r1 = *(const int4*)(rows + i0 + 4);
            int4   c0 = *(const int4*)(cols + i0);
            int4   c1 = *(const int4*)(cols + i0 + 4);
            float vv[8] = {v0.x, v0.y, v0.z, v0.w, v1.x, v1.y, v1.z, v1.w};
            int   rr[8] = {r0.x, r0.y, r0.z, r0.w, r1.x, r1.y, r1.z, r1.w};
            int   cc[8] = {c0.x, c0.y, c0.z, c0.w, c1.x, c1.y, c1.z, c1.w};
#pragma unroll
            for (int k = 0; k < 8; k++) {
                int bin = rr[k] >> 5;
                unsigned pos = atomicAdd(&scnt[bin], 1u);
                float2 e = make_float2(vv[k],
                    __int_as_float(cc[k] | ((rr[k] & 31) << 13)));
                if (pos < DEPTH_C) sbuf[bin * DEPTH_C + pos] = e;
                else {                                   // ~never
                    unsigned p = atomicAdd(&g_ccur[bin], 1u);
                    if (p < CCAP) g_cbucket[(size_t)bin * CCAP + p] = e;
                }
            }
        } else {
            for (int k = 0; k < 8; k++) {
                int i = i0 + k;
                if (i < end) {
                    int r = rows[i], c = cols[i];
                    int bin = r >> 5;
                    unsigned pos = atomicAdd(&scnt[bin], 1u);
                    float2 e = make_float2(vals[i],
                        __int_as_float(c | ((r & 31) << 13)));
                    if (pos < DEPTH_C) sbuf[bin * DEPTH_C + pos] = e;
                    else {
                        unsigned p = atomicAdd(&g_ccur[bin], 1u);
                        if (p < CCAP) g_cbucket[(size_t)bin * CCAP + p] = e;
                    }
                }
            }
        }
        __syncthreads();

        if (tid < NCB) {
            unsigned c = min(scnt[tid], (unsigned)DEPTH_C);
            sbase[tid] = c ? atomicAdd(&g_ccur[tid], c) : 0u;
        }
        __syncthreads();

        for (int b = w * 8; b < w * 8 + 8; b++) {
            unsigned cnt = min(scnt[b], (unsigned)DEPTH_C);
            if (cnt == 0) continue;
            size_t dst = (size_t)b * CCAP + sbase[b];
            if (lane < cnt)
                g_cbucket[dst + lane] = sbuf[b * DEPTH_C + lane];
            if (cnt > 32 && lane + 32 < cnt)
                g_cbucket[dst + lane + 32] = sbuf[b * DEPTH_C + lane + 32];
        }
        __syncthreads();
    }
}

// ---------------------------------------------------------------------------
// Kernel 4 (ncu slot): fused refine + gather. Grid 512 = (bin, segment-half).
// Each block streams its half of the bin's entries, stages by row-in-bin,
// drains with 8 loads in flight, and red-adds 32-row partials into g_z.
__global__ void __launch_bounds__(512, 4) k_fuse() {
    extern __shared__ float2 stg[];              // 32 * DEPTH_F
    __shared__ unsigned scnt[32];
    int tid  = threadIdx.x;
    int w    = tid >> 5;
    int lane = tid & 31;
    int half = lane >> 4;
    int b    = lane & 15;
    int cb   = blockIdx.x >> 1;
    int seg  = blockIdx.x & 1;

    int cnt = min(g_ccur[cb], (unsigned)CCAP);
    int s_beg = seg ? (cnt >> 1) : 0;
    int s_end = seg ? cnt : (cnt >> 1);
    const float2* __restrict__ src = g_cbucket + (size_t)cb * CCAP;

    float acc0 = 0.0f, acc1 = 0.0f;              // rows cb*32+2w, +2w+1

    for (int base = s_beg; base < s_end; base += TF) {
        if (tid < 32) scnt[tid] = 0;
        __syncthreads();

        int n = min(TF, s_end - base);
        for (int k = tid; k < n; k += 512) {     // coalesced stream
            float2 e = src[base + k];
            int rl = (__float_as_int(e.y) >> 13) & 31;
            unsigned pos = atomicAdd(&scnt[rl], 1u);
            if (pos < DEPTH_F) {
                stg[rl * DEPTH_F + pos] = e;
            } else {                             // ~never: direct z accumulation
                int c = __float_as_int(e.y) & 8191;
                float v = e.x;
                const float4* s4 = reinterpret_cast<const float4*>(g_state_T + c * BATCH);
                float4 s0 = s4[0], s1 = s4[1], s2 = s4[2], s3 = s4[3];
                float* zp = g_z + ((cb << 5) | rl) * BATCH;
                red_add_v4(zp + 0,  v * s0.x, v * s0.y, v * s0.z, v * s0.w);
                red_add_v4(zp + 4,  v * s1.x, v * s1.y, v * s1.z, v * s1.w);
                red_add_v4(zp + 8,  v * s2.x, v * s2.y, v * s2.z, v * s2.w);
                red_add_v4(zp + 12, v * s3.x, v * s3.y, v * s3.z, v * s3.w);
            }
        }
        __syncthreads();

        // Drain: warp w -> rows 2w, 2w+1; half-warp = one entry; 8 in flight.
#pragma unroll
        for (int rr = 0; rr < 2; rr++) {
            int rl = (w << 1) | rr;
            int m = min(scnt[rl], (unsigned)DEPTH_F);
            const float2* row = stg + rl * DEPTH_F;
            float acc = 0.0f;
            int j = half;
            for (; j + 14 < m; j += 16) {
                float2 e0 = row[j];
                float2 e1 = row[j + 2];
                float2 e2 = row[j + 4];
                float2 e3 = row[j + 6];
                float2 e4 = row[j + 8];
                float2 e5 = row[j + 10];
                float2 e6 = row[j + 12];
                float2 e7 = row[j + 14];
                float s0 = g_state_T[(__float_as_int(e0.y) & 8191) * BATCH + b];
                float s1 = g_state_T[(__float_as_int(e1.y) & 8191) * BATCH + b];
                float s2 = g_state_T[(__float_as_int(e2.y) & 8191) * BATCH + b];
                float s3 = g_state_T[(__float_as_int(e3.y) & 8191) * BATCH + b];
                float s4 = g_state_T[(__float_as_int(e4.y) & 8191) * BATCH + b];
                float s5 = g_state_T[(__float_as_int(e5.y) & 8191) * BATCH + b];
                float s6 = g_state_T[(__float_as_int(e6.y) & 8191) * BATCH + b];
                float s7 = g_state_T[(__float_as_int(e7.y) & 8191) * BATCH + b];
                acc = fmaf(e0.x, s0, acc);
                acc = fmaf(e1.x, s1, acc);
                acc = fmaf(e2.x, s2, acc);
                acc = fmaf(e3.x, s3, acc);
                acc = fmaf(e4.x, s4, acc);
                acc = fmaf(e5.x, s5, acc);
                acc = fmaf(e6.x, s6, acc);
                acc = fmaf(e7.x, s7, acc);
            }
            for (; j < m; j += 2) {
                float2 e = row[j];
                acc = fmaf(e.x, g_state_T[(__float_as_int(e.y) & 8191) * BATCH + b], acc);
            }
            if (rr) acc1 += acc; else acc0 += acc;
        }
        __syncthreads();
    }

    // Flush 32-row partials into g_z (scalar lane reductions).
    acc0 += __shfl_xor_sync(0xffffffffu, acc0, 16);
    acc1 += __shfl_xor_sync(0xffffffffu, acc1, 16);
    if (lane < BATCH) {
        int r0 = (cb << 5) | (w << 1);
        red_add_f32(g_z + r0 * BATCH + lane, acc0);
        red_add_f32(g_z + (r0 + 1) * BATCH + lane, acc1);
    }
}

// ---------------------------------------------------------------------------
// Kernel 5: epilogue  out[b,r] = 0.1*state[b,r] + 0.9*erf(z[r,b])
__global__ void k_final(const float* __restrict__ state,
                        float* __restrict__ out) {
    int i = blockIdx.x * blockDim.x + threadIdx.x;
    if (i >= BATCH * N_RES) return;
    int b = i >> 13;
    int r = i & (N_RES - 1);
    float z = g_z[r * BATCH + b];
    out[i] = (1.0f - LEAK) * state[i] + LEAK * erff(z);
}

// ---------------------------------------------------------------------------
extern "C" void kernel_launch(void* const* d_in, const int* in_sizes, int n_in,
                              void* d_out, int out_size) {
    const float* state    = (const float*)d_in[0];
    const float* x        = (const float*)d_in[1];
    const float* res_vals = (const float*)d_in[2];
    const int*   res_rows = (const int*)  d_in[3];
    const int*   res_cols = (const int*)  d_in[4];
    const float* res_bias = (const float*)d_in[5];
    const float* in_vals  = (const float*)d_in[6];
    const int*   in_rows  = (const int*)  d_in[7];
    const int*   in_cols  = (const int*)  d_in[8];
    const float* in_bias  = (const float*)d_in[9];
    float* out = (float*)d_out;

    int res_nnz = in_sizes[2];
    int in_nnz  = in_sizes[6];
    int csz = ((res_nnz + NCH - 1) / NCH + 7) & ~7;

    static int smem_set = 0;
    if (!smem_set) {
        cudaFuncSetAttribute(k_coarse, cudaFuncAttributeMaxDynamicSharedMemorySize, COARSE_SMEM);
        cudaFuncSetAttribute(k_fuse,   cudaFuncAttributeMaxDynamicSharedMemorySize, FUSE_SMEM);
        smem_set = 1;
    }

    // Launch order: slot 4 (ncu capture) = k_fuse.
    k_init<<<(N_RES * BATCH + 255) / 256, 256>>>(state, x, res_bias, in_bias);

    k_in_spmm<<<(in_nnz + 255) / 256, 256>>>(in_vals, in_rows, in_cols, in_nnz);

    k_coarse<<<NCH, 1024, COARSE_SMEM>>>(res_vals, res_rows, res_cols, res_nnz, csz);

    k_fuse<<<NCB * NSEG, 512, FUSE_SMEM>>>();

    k_final<<<(BATCH * N_RES + 255) / 256, 256>>>(state, out);
}